// round 16
// baseline (speedup 1.0000x reference)
#include <cuda_runtime.h>
#include <cuda_bf16.h>
#include <cuda_fp16.h>
#include <cstdint>

// Problem constants
#define BB 4
#define LL 2048
#define DM 1024
#define DI 2048        // D_INNER
#define DS 16          // D_STATE
#define DC 4           // D_CONV
#define DTR 64         // DT_RANK
#define MM (BB*LL)     // 8192 rows
#define XDBL_W (DTR + 2*DS)   // 96
#define NCH 32         // scan chunks
#define NCHB 5         // log2(NCH)
#define CL (LL/NCH)    // 64 steps per chunk
#define TS 16          // timesteps staged per tile
#define KSPL 8         // split-K factor for GEMM2

// ---------------- scratch (static device globals; no allocations) ----------------
__device__ __align__(16) float g_xdbl[(size_t)MM * XDBL_W];   // dt_in | B | C
__device__ __align__(16) float g_dt[(size_t)MM * DI];         // softplus dt
__device__ __align__(16) float g_H[(size_t)BB * NCH * DS * DI];
__device__ __align__(16) float g_P[(size_t)BB * NCH * DS * DI];
__device__ __align__(16) float g_Hpre[(size_t)BB * NCH * DS * DI]; // chunk-start states
__device__ __align__(16) float g_Atab[(size_t)DS * DI];       // -exp(logA), transposed
__device__ __align__(16) float g_part[(size_t)KSPL * MM * 128];  // split-K partials

// fp16 buffers
__device__ __align__(16) __half g_xch[(size_t)MM * DI];       // x_val (pre-conv), fp16
__device__ __align__(16) __half g_resg[(size_t)MM * DI];      // silu(res), fp16
__device__ __align__(16) __half g_xh [(size_t)MM * DM];
__device__ __align__(16) __half g_xvh[(size_t)MM * DI];       // conv+silu output (u)
__device__ __align__(16) __half g_dth[(size_t)MM * DTR];
__device__ __align__(16) __half g_ygh[(size_t)MM * DI];

// transposed fp16 weights, layout (N, K) row-major
__device__ __align__(16) __half g_winT[(size_t)(2*DI) * DM];
__device__ __align__(16) __half g_wxT[(size_t)128 * DI];      // rows 96..127 stay zero
__device__ __align__(16) __half g_wdtT[(size_t)DI * DTR];
__device__ __align__(16) __half g_woutT[(size_t)DM * DI];

// ===================== low-level helpers =====================
typedef unsigned long long ull;

__device__ __forceinline__ uint32_t smem_u32(const void* p) {
    uint32_t a;
    asm("{ .reg .u64 t; cvta.to.shared.u64 t, %1; cvt.u32.u64 %0, t; }" : "=r"(a) : "l"(p));
    return a;
}
__device__ __forceinline__ void cpa16(uint32_t s, const void* g) {
    asm volatile("cp.async.cg.shared.global [%0], [%1], 16;" :: "r"(s), "l"(g));
}
#define CP_COMMIT() asm volatile("cp.async.commit_group;")
#define CP_WAIT(n)  asm volatile("cp.async.wait_group %0;" :: "n"(n))

__device__ __forceinline__ void ldsm4(uint32_t* r, uint32_t addr) {
    asm volatile("ldmatrix.sync.aligned.m8n8.x4.shared.b16 {%0,%1,%2,%3}, [%4];"
        : "=r"(r[0]), "=r"(r[1]), "=r"(r[2]), "=r"(r[3]) : "r"(addr));
}
__device__ __forceinline__ void mma16816(float* d, const uint32_t* a, const uint32_t* b) {
    asm volatile(
        "mma.sync.aligned.m16n8k16.row.col.f32.f16.f16.f32 "
        "{%0,%1,%2,%3}, {%4,%5,%6,%7}, {%8,%9}, {%0,%1,%2,%3};"
        : "+f"(d[0]), "+f"(d[1]), "+f"(d[2]), "+f"(d[3])
        : "r"(a[0]), "r"(a[1]), "r"(a[2]), "r"(a[3]), "r"(b[0]), "r"(b[1]));
}
__device__ __forceinline__ float silu_f(float v) {
    return v * (1.0f / (1.0f + __expf(-v)));
}
__device__ __forceinline__ float softplus_f(float v) {
    return (v > 20.0f) ? v : __logf(1.0f + __expf(v));
}

// ---- packed f32x2 helpers ----
__device__ __forceinline__ ull pk2(float x, float y) {
    ull r; asm("mov.b64 %0, {%1, %2};" : "=l"(r) : "f"(x), "f"(y)); return r;
}
__device__ __forceinline__ void upk2(ull v, float& x, float& y) {
    asm("mov.b64 {%0, %1}, %2;" : "=f"(x), "=f"(y) : "l"(v));
}
__device__ __forceinline__ ull fma2(ull a, ull b, ull c) {
    ull d; asm("fma.rn.f32x2 %0, %1, %2, %3;" : "=l"(d) : "l"(a), "l"(b), "l"(c)); return d;
}
__device__ __forceinline__ ull mul2(ull a, ull b) {
    ull d; asm("mul.rn.f32x2 %0, %1, %2;" : "=l"(d) : "l"(a), "l"(b)); return d;
}

// ================= HMMA GEMM: C(M,N) = A(M,K) @ B(N,K)^T, fp16, 2-stage =================
#define ASZ 16384
#define STAGE 32768
#define HG_SMEM 65536

__global__ void __launch_bounds__(256, 2)
hgemm(const __half* __restrict__ A, const __half* __restrict__ B,
      float* __restrict__ C, __half* __restrict__ C2,
      int N, int K, int ldc,
      const float* __restrict__ bias, int epi, int kslice, size_t zstride)
{
    extern __shared__ char smem[];
    const uint32_t sb = smem_u32(smem);
    const int tid  = threadIdx.x;
    const int wid  = tid >> 5;
    const int lane = tid & 31;
    const int row0 = blockIdx.y * 128;
    const int col0 = blockIdx.x * 128;
    const int wm = wid & 1;
    const int wn = wid >> 1;

    const int kbase = blockIdx.z * kslice;
    C += (size_t)blockIdx.z * zstride;
    const int KT = kslice >> 6;

    float acc[4][4][4];
    #pragma unroll
    for (int i = 0; i < 4; i++)
        #pragma unroll
        for (int j = 0; j < 4; j++)
            #pragma unroll
            for (int q = 0; q < 4; q++) acc[i][j][q] = 0.0f;

    auto load_stage = [&](int s, int k0) {
        const uint32_t base = sb + (uint32_t)s * STAGE;
        #pragma unroll
        for (int i = 0; i < 4; i++) {
            const int lin = tid + i * 256;
            const int r = lin >> 3, c = lin & 7;
            const uint32_t so = (uint32_t)(r * 128 + ((c ^ (r & 7)) << 4));
            cpa16(base + so,       A + (size_t)(row0 + r) * K + k0 + c * 8);
            cpa16(base + ASZ + so, B + (size_t)(col0 + r) * K + k0 + c * 8);
        }
        CP_COMMIT();
    };

    auto compute_stage = [&](int s) {
        const uint32_t aBase = sb + (uint32_t)s * STAGE;
        const uint32_t bBase = aBase + ASZ;
        #pragma unroll
        for (int kss = 0; kss < 4; kss++) {
            const int ks = (kss + wid) & 3;
            uint32_t ah[4][4];
            #pragma unroll
            for (int mt = 0; mt < 4; mt++) {
                const int R = wm * 64 + mt * 16 + (lane & 15);
                const int c = ks * 2 + (lane >> 4);
                ldsm4(ah[mt], aBase + (uint32_t)(R * 128 + ((c ^ (R & 7)) << 4)));
            }
            #pragma unroll
            for (int g = 0; g < 2; g++) {
                const int R = wn * 32 + g * 16 + (lane & 7) + ((lane >> 4) & 1) * 8;
                const int c = ks * 2 + ((lane >> 3) & 1);
                uint32_t bh[4];
                ldsm4(bh, bBase + (uint32_t)(R * 128 + ((c ^ (R & 7)) << 4)));
                #pragma unroll
                for (int mt = 0; mt < 4; mt++)
                    #pragma unroll
                    for (int sub = 0; sub < 2; sub++)
                        mma16816(acc[mt][g * 2 + sub], ah[mt], &bh[sub * 2]);
            }
        }
    };

    load_stage(0, kbase);
    for (int kt = 0; kt < KT; kt++) {
        if (kt + 1 < KT) {
            load_stage((kt + 1) & 1, kbase + (kt + 1) * 64);
            CP_WAIT(1);
        } else {
            CP_WAIT(0);
        }
        __syncthreads();
        compute_stage(kt & 1);
        __syncthreads();
    }

    // epi: 0 = fp32 store; 1 = bias+softplus fp32 store;
    //      2 = split fp16 store: x-half -> C2h (cols 0..DI-1), res-half -> silu -> C2 (cols DI..)
    const bool split = (epi == 2);
    const bool resblk = split && (col0 >= DI);
    #pragma unroll
    for (int mt = 0; mt < 4; mt++) {
        const int row = row0 + wm * 64 + mt * 16 + (lane >> 2);
        #pragma unroll
        for (int j = 0; j < 4; j++) {
            const int col = col0 + wn * 32 + j * 8 + (lane & 3) * 2;
            float v0 = acc[mt][j][0], v1 = acc[mt][j][1];
            float v2 = acc[mt][j][2], v3 = acc[mt][j][3];
            if (epi == 1) {
                const float b0 = bias[col], b1 = bias[col + 1];
                v0 = softplus_f(v0 + b0);
                v1 = softplus_f(v1 + b1);
                v2 = softplus_f(v2 + b0);
                v3 = softplus_f(v3 + b1);
            }
            if (split) {
                if (resblk) {
                    const int rc = col - DI;
                    __half2 h0 = __floats2half2_rn(silu_f(v0), silu_f(v1));
                    __half2 h1 = __floats2half2_rn(silu_f(v2), silu_f(v3));
                    *(__half2*)(C2 + (size_t)row * DI + rc)       = h0;
                    *(__half2*)(C2 + (size_t)(row + 8) * DI + rc) = h1;
                } else {
                    // x-half: store fp16 into C (reinterpreted as half*) at stride DI
                    __half* Ch = (__half*)C;
                    __half2 h0 = __floats2half2_rn(v0, v1);
                    __half2 h1 = __floats2half2_rn(v2, v3);
                    *(__half2*)(Ch + (size_t)row * DI + col)       = h0;
                    *(__half2*)(Ch + (size_t)(row + 8) * DI + col) = h1;
                }
            } else {
                *(float2*)(C + (size_t)row * ldc + col)       = make_float2(v0, v1);
                *(float2*)(C + (size_t)(row + 8) * ldc + col) = make_float2(v2, v3);
            }
        }
    }
}

// ---------------- split-K reduce for GEMM2 -> xdbl + fused dt fp16 ----------------
__global__ void __launch_bounds__(256)
reduceK(const float* __restrict__ part, float* __restrict__ xdbl, __half* __restrict__ dth)
{
    const int i = blockIdx.x * 256 + threadIdx.x;
    if (i >= MM * XDBL_W) return;
    const int r = i / XDBL_W, c = i - r * XDBL_W;
    const size_t o = (size_t)r * 128 + c;
    float s = 0.0f;
    #pragma unroll
    for (int q = 0; q < KSPL; q++) s += part[o + (size_t)q * MM * 128];
    xdbl[i] = s;
    if (c < DTR) dth[(size_t)r * DTR + c] = __float2half_rn(s);
}

// ---------------- weight transpose -> fp16: W(K,N) -> T(N,K) ----------------
__global__ void __launch_bounds__(256)
ttrans(const float* __restrict__ W, __half* __restrict__ T, int K, int N)
{
    __shared__ float t[32][33];
    const int n0 = blockIdx.x * 32;
    const int k0 = blockIdx.y * 32;
    const int tx = threadIdx.x & 31;
    const int ty = threadIdx.x >> 5;
    #pragma unroll
    for (int i = 0; i < 32; i += 8)
        t[ty + i][tx] = W[(size_t)(k0 + ty + i) * N + (n0 + tx)];
    __syncthreads();
    #pragma unroll
    for (int i = 0; i < 32; i += 8)
        T[(size_t)(n0 + ty + i) * K + (k0 + tx)] = __float2half_rn(t[tx][ty + i]);
}

// ---------------- fp32 -> fp16 (dense) ----------------
__global__ void __launch_bounds__(256)
to_half(const float* __restrict__ in, __half* __restrict__ h, int n4)
{
    const int i = blockIdx.x * blockDim.x + threadIdx.x;
    if (i >= n4) return;
    const float4 v = ((const float4*)in)[i];
    __half2 a = __floats2half2_rn(v.x, v.y);
    __half2 b = __floats2half2_rn(v.z, v.w);
    ((uint2*)h)[i] = make_uint2(*(uint32_t*)&a, *(uint32_t*)&b);
}

// ---------------- A table ----------------
__global__ void __launch_bounds__(256)
a_prep(const float* __restrict__ logA, float* __restrict__ Atab)
{
    const int i = blockIdx.x * 256 + threadIdx.x;
    if (i >= DS * DI) return;
    const int d = i & (DI - 1);
    const int n = i >> 11;
    Atab[(size_t)n * DI + d] = -__expf(logA[(size_t)d * DS + n]);
}

// ---------------- causal depthwise conv (k=4) + SiLU, fp16 in/out, 8 outputs/thread ----------------
// grid: (DI/256, LL/8, BB); block 256 = one d per thread.
__global__ void __launch_bounds__(256)
conv_silu_kernel(const __half* __restrict__ xch, const float* __restrict__ w,
                 const float* __restrict__ bias, __half* __restrict__ oh)
{
    const int d  = blockIdx.x * 256 + threadIdx.x;
    const int l0 = blockIdx.y * 8;
    const int b  = blockIdx.z;

    const float w0 = w[d * DC + 0], w1 = w[d * DC + 1], w2 = w[d * DC + 2], w3 = w[d * DC + 3];
    const float bv = bias[d];

    const size_t base = ((size_t)b * LL + l0) * DI + d;
    // taps needed: x[l0-3 .. l0+7]  (11 values)
    float xv[11];
    #pragma unroll
    for (int i = 0; i < 11; i++) {
        const int l = l0 + i - 3;
        xv[i] = (l >= 0) ? __half2float(xch[base + (size_t)(i - 3) * DI]) : 0.0f;
    }
    #pragma unroll
    for (int j = 0; j < 8; j++) {
        float acc = bv;
        acc = fmaf(xv[j + 0], w0, acc);
        acc = fmaf(xv[j + 1], w1, acc);
        acc = fmaf(xv[j + 2], w2, acc);
        acc = fmaf(xv[j + 3], w3, acc);
        oh[base + (size_t)j * DI] = __float2half_rn(silu_f(acc));
    }
}

// ================= chunked selective scan (NCH=32) =================
__device__ __forceinline__ void make_e2(bool pw, float dts, float A0, const float* A, ull* e2)
{
    if (pw) {
        const float e1 = __expf(dts * A0);
        const float es = e1 * e1;
        const ull es2 = pk2(es, es);
        e2[0] = pk2(e1, es);
        #pragma unroll
        for (int k = 1; k < 8; k++) e2[k] = mul2(e2[k - 1], es2);
    } else {
        #pragma unroll
        for (int k = 0; k < 8; k++)
            e2[k] = pk2(__expf(dts * A[2 * k]), __expf(dts * A[2 * k + 1]));
    }
}

__global__ void __launch_bounds__(256)
scan_p1(const float* __restrict__ dt, const __half* __restrict__ u,
        const float* __restrict__ xdbl, const float* __restrict__ Atab,
        float* __restrict__ H, float* __restrict__ P)
{
    __shared__ float sB[2][TS * 16];
    const int bid = blockIdx.x;
    const int tid = threadIdx.x;
    const int d = ((bid & 7) << 8) + tid;
    const int c = (bid >> 3) & (NCH - 1);
    const int b = bid >> (3 + NCHB);

    float A[DS];
    #pragma unroll
    for (int n = 0; n < DS; n++) A[n] = Atab[(size_t)n * DI + d];
    const float A0 = A[0];
    bool pw = true;
    #pragma unroll
    for (int n = 1; n < DS; n++)
        pw = pw && (fabsf(A[n] - (float)(n + 1) * A0) <= 1e-5f * fabsf(A[n]));

    ull h2[8];
    #pragma unroll
    for (int k = 0; k < 8; k++) h2[k] = 0ull;
    float sdt = 0.0f;

    const size_t m0 = (size_t)b * LL + c * CL;
    const uint32_t sbB0 = smem_u32(&sB[0][0]);
    const uint32_t sbB1 = smem_u32(&sB[1][0]);

    if (tid < 64) {
        const int step = tid >> 2, f = (tid & 3) * 4;
        cpa16(sbB0 + tid * 16, xdbl + (m0 + step) * XDBL_W + DTR + f);
    }
    CP_COMMIT();

    for (int t0 = 0; t0 < CL; t0 += TS) {
        const int buf = (t0 / TS) & 1;
        CP_WAIT(0);
        __syncthreads();
        if (t0 + TS < CL && tid < 64) {
            const int step = tid >> 2, f = (tid & 3) * 4;
            cpa16((buf ? sbB0 : sbB1) + tid * 16,
                  xdbl + (m0 + t0 + TS + step) * XDBL_W + DTR + f);
        }
        CP_COMMIT();

        float dtv[TS];
        __half uvh[TS];
        #pragma unroll
        for (int s = 0; s < TS; s++) dtv[s] = dt[(m0 + t0 + s) * DI + d];
        #pragma unroll
        for (int s = 0; s < TS; s++) uvh[s] = u[(m0 + t0 + s) * DI + d];

        #pragma unroll
        for (int s = 0; s < TS; s++) {
            const float dts = dtv[s];
            const float dtu = dts * __half2float(uvh[s]);
            sdt += dts;
            ull e2[8];
            make_e2(pw, dts, A0, A, e2);
            const ull dtu2 = pk2(dtu, dtu);
            const ull* B2 = (const ull*)&sB[buf][s * 16];
            #pragma unroll
            for (int k = 0; k < 8; k++)
                h2[k] = fma2(e2[k], h2[k], mul2(dtu2, B2[k]));
        }
    }
    const size_t o = ((size_t)(b * NCH + c) * DS) * DI + d;
    #pragma unroll
    for (int k = 0; k < 8; k++) {
        float hx, hy;
        upk2(h2[k], hx, hy);
        H[o + (size_t)(2 * k) * DI]     = hx;
        H[o + (size_t)(2 * k + 1) * DI] = hy;
    }
    #pragma unroll
    for (int n = 0; n < DS; n++)
        P[o + (size_t)n * DI] = __expf(A[n] * sdt);
}

__global__ void __launch_bounds__(256)
scan_mid(const float* __restrict__ H, const float* __restrict__ P, float* __restrict__ Hpre)
{
    const int idx = blockIdx.x * 256 + threadIdx.x;   // BB*DS*DI = 131072
    const int d = idx & (DI - 1);
    const int rest = idx >> 11;
    const int n = rest & (DS - 1);
    const int b = rest >> 4;

    float h = 0.0f;
    for (int c = 0; c < NCH; c++) {
        const size_t o = ((size_t)((b * NCH + c) * DS) + n) * DI + d;
        Hpre[o] = h;
        h = fmaf(P[o], h, H[o]);
    }
}

__global__ void __launch_bounds__(256)
scan_p2(const float* __restrict__ dt, const __half* __restrict__ u,
        const float* __restrict__ xdbl, const float* __restrict__ Atab,
        const float* __restrict__ Dp, const __half* __restrict__ resg,
        const float* __restrict__ Hpre,
        __half* __restrict__ ygh)
{
    __shared__ float sBC[2][TS * 32];
    const int bid = blockIdx.x;
    const int tid = threadIdx.x;
    const int d = ((bid & 7) << 8) + tid;
    const int c = (bid >> 3) & (NCH - 1);
    const int b = bid >> (3 + NCHB);

    float A[DS];
    #pragma unroll
    for (int n = 0; n < DS; n++) A[n] = Atab[(size_t)n * DI + d];
    const float A0 = A[0];
    bool pw = true;
    #pragma unroll
    for (int n = 1; n < DS; n++)
        pw = pw && (fabsf(A[n] - (float)(n + 1) * A0) <= 1e-5f * fabsf(A[n]));

    ull h2[8];
    {
        const size_t o = ((size_t)(b * NCH + c) * DS) * DI + d;
        #pragma unroll
        for (int k = 0; k < 8; k++)
            h2[k] = pk2(Hpre[o + (size_t)(2 * k) * DI], Hpre[o + (size_t)(2 * k + 1) * DI]);
    }
    const float Dv = Dp[d];
    const size_t m0 = (size_t)b * LL + c * CL;
    const uint32_t sb0 = smem_u32(&sBC[0][0]);
    const uint32_t sb1 = smem_u32(&sBC[1][0]);

    if (tid < 128) {
        const int step = tid >> 3, f = (tid & 7) * 4;
        cpa16(sb0 + tid * 16, xdbl + (m0 + step) * XDBL_W + DTR + f);
    }
    CP_COMMIT();

    for (int t0 = 0; t0 < CL; t0 += TS) {
        const int buf = (t0 / TS) & 1;
        CP_WAIT(0);
        __syncthreads();
        if (t0 + TS < CL && tid < 128) {
            const int step = tid >> 3, f = (tid & 7) * 4;
            cpa16((buf ? sb0 : sb1) + tid * 16,
                  xdbl + (m0 + t0 + TS + step) * XDBL_W + DTR + f);
        }
        CP_COMMIT();

        float dtv[TS];
        __half uvh[TS], gvh[TS];
        #pragma unroll
        for (int s = 0; s < TS; s++) dtv[s] = dt[(m0 + t0 + s) * DI + d];
        #pragma unroll
        for (int s = 0; s < TS; s++) uvh[s] = u[(m0 + t0 + s) * DI + d];
        #pragma unroll
        for (int s = 0; s < TS; s++) gvh[s] = resg[(m0 + t0 + s) * DI + d];

        #pragma unroll
        for (int s = 0; s < TS; s++) {
            const float dts = dtv[s];
            const float uv  = __half2float(uvh[s]);
            const float dtu = dts * uv;
            ull e2[8];
            make_e2(pw, dts, A0, A, e2);
            const ull dtu2 = pk2(dtu, dtu);
            const ull* B2 = (const ull*)&sBC[buf][s * 32];
            const ull* C2 = B2 + 8;
            ull y2 = 0ull;
            #pragma unroll
            for (int k = 0; k < 8; k++) {
                h2[k] = fma2(e2[k], h2[k], mul2(dtu2, B2[k]));
                y2 = fma2(C2[k], h2[k], y2);
            }
            float yx, yy;
            upk2(y2, yx, yy);
            float y = yx + yy;
            y = fmaf(Dv, uv, y);
            ygh[(m0 + t0 + s) * DI + d] = __float2half_rn(y * __half2float(gvh[s]));
        }
    }
}

// ---------------- host launcher ----------------
extern "C" void kernel_launch(void* const* d_in, const int* in_sizes, int n_in,
                              void* d_out, int out_size)
{
    const float* x      = (const float*)d_in[0];
    const float* W_in   = (const float*)d_in[1];
    const float* conv_w = (const float*)d_in[2];
    const float* conv_b = (const float*)d_in[3];
    const float* W_x    = (const float*)d_in[4];
    const float* W_dt   = (const float*)d_in[5];
    const float* b_dt   = (const float*)d_in[6];
    const float* logA   = (const float*)d_in[7];
    const float* Dp     = (const float*)d_in[8];
    const float* W_out  = (const float*)d_in[9];
    float* out = (float*)d_out;

    cudaFuncSetAttribute(hgemm, cudaFuncAttributeMaxDynamicSharedMemorySize, HG_SMEM);

    float *xdbl, *dtb, *Hb, *Pb, *Hpre, *Atab, *part;
    cudaGetSymbolAddress((void**)&xdbl, g_xdbl);
    cudaGetSymbolAddress((void**)&dtb,  g_dt);
    cudaGetSymbolAddress((void**)&Hb,   g_H);
    cudaGetSymbolAddress((void**)&Pb,   g_P);
    cudaGetSymbolAddress((void**)&Hpre, g_Hpre);
    cudaGetSymbolAddress((void**)&Atab, g_Atab);
    cudaGetSymbolAddress((void**)&part, g_part);

    __half *xch, *resg, *xh, *xvh, *dth, *ygh;
    cudaGetSymbolAddress((void**)&xch,  g_xch);
    cudaGetSymbolAddress((void**)&resg, g_resg);
    cudaGetSymbolAddress((void**)&xh,  g_xh);
    cudaGetSymbolAddress((void**)&xvh, g_xvh);
    cudaGetSymbolAddress((void**)&dth, g_dth);
    cudaGetSymbolAddress((void**)&ygh, g_ygh);

    __half *winT, *wxT, *wdtT, *woutT;
    cudaGetSymbolAddress((void**)&winT,  g_winT);
    cudaGetSymbolAddress((void**)&wxT,   g_wxT);
    cudaGetSymbolAddress((void**)&wdtT,  g_wdtT);
    cudaGetSymbolAddress((void**)&woutT, g_woutT);

    // 1) W_in transpose
    ttrans<<<dim3((2*DI)/32, DM/32), 256>>>(W_in, winT, DM, 2*DI);
    // 2) x -> fp16
    to_half<<<(MM*DM/4 + 255)/256, 256>>>(x, xh, MM*DM/4);
    // 3) W_out transpose
    ttrans<<<dim3(DM/32, DI/32), 256>>>(W_out, woutT, DI, DM);

    // 4) GEMM1: x @ W_in: x-half -> xch (fp16), res-half -> silu -> resg (fp16)
    hgemm<<<dim3((2*DI)/128, MM/128), 256, HG_SMEM>>>(
        xh, winT, (float*)xch, resg, 2*DI, DM, DI, nullptr, 2, DM, 0);

    // 5) causal conv + silu -> xvh (fp16), fp16 input, 8 outputs per thread
    conv_silu_kernel<<<dim3(DI/256, LL/8, BB), 256>>>(xch, conv_w, conv_b, xvh);

    // 6) W_x transpose
    ttrans<<<dim3(XDBL_W/32, DI/32), 256>>>(W_x, wxT, DI, XDBL_W);

    // 7) GEMM2: xval @ W_x -> partials (split-K=8)
    hgemm<<<dim3(1, MM/128, KSPL), 256, HG_SMEM>>>(
        xvh, wxT, part, nullptr, 128, DI, 128, nullptr, 0, DI/KSPL, (size_t)MM*128);
    // 8) reduce -> xdbl + dt fp16
    reduceK<<<(MM*XDBL_W + 255)/256, 256>>>(part, xdbl, dth);

    // 9) W_dt transpose
    ttrans<<<dim3(DI/32, DTR/32), 256>>>(W_dt, wdtT, DTR, DI);

    // 10) GEMM3: softplus(dt_in @ W_dt + b_dt) -> dt
    hgemm<<<dim3(DI/128, MM/128), 256, HG_SMEM>>>(
        dth, wdtT, dtb, nullptr, DI, DTR, DI, b_dt, 1, DTR, 0);

    // 11) A table
    a_prep<<<(DS*DI + 255)/256, 256>>>(logA, Atab);

    // 12-14) chunked selective scan
    scan_p1<<<BB * NCH * (DI/256), 256>>>(dtb, xvh, xdbl, Atab, Hb, Pb);
    scan_mid<<<(BB*DS*DI)/256, 256>>>(Hb, Pb, Hpre);
    scan_p2<<<BB * NCH * (DI/256), 256>>>(dtb, xvh, xdbl, Atab, Dp, resg, Hpre, ygh);

    // 15) GEMM4: yg @ W_out -> out
    hgemm<<<dim3(DM/128, MM/128), 256, HG_SMEM>>>(
        ygh, woutT, out, nullptr, DM, DI, DM, nullptr, 0, DI, 0);
}

// round 17
// speedup vs baseline: 1.0372x; 1.0372x over previous
#include <cuda_runtime.h>
#include <cuda_bf16.h>
#include <cuda_fp16.h>
#include <cstdint>

// Problem constants
#define BB 4
#define LL 2048
#define DM 1024
#define DI 2048        // D_INNER
#define DS 16          // D_STATE
#define DC 4           // D_CONV
#define DTR 64         // DT_RANK
#define MM (BB*LL)     // 8192 rows
#define XDBL_W (DTR + 2*DS)   // 96
#define NCH 32         // scan chunks
#define NCHB 5         // log2(NCH)
#define CL (LL/NCH)    // 64 steps per chunk
#define TS 16          // timesteps staged per tile
#define KSPL 8         // split-K factor for GEMM2

// ---------------- scratch (static device globals; no allocations) ----------------
__device__ __align__(16) float g_xc[(size_t)MM * DI];         // x_val (pre-conv), fp32
__device__ __align__(16) float g_xdbl[(size_t)MM * XDBL_W];   // dt_in | B | C
__device__ __align__(16) float g_dt[(size_t)MM * DI];         // softplus dt
__device__ __align__(16) float g_H[(size_t)BB * NCH * DS * DI];
__device__ __align__(16) float g_P[(size_t)BB * NCH * DS * DI];
__device__ __align__(16) float g_Hpre[(size_t)BB * NCH * DS * DI]; // chunk-start states
__device__ __align__(16) float g_Atab[(size_t)DS * DI];       // -exp(logA), transposed
__device__ __align__(16) float g_part[(size_t)KSPL * MM * 128];  // split-K partials

// fp16 buffers
__device__ __align__(16) __half g_resg[(size_t)MM * DI];      // silu(res), fp16
__device__ __align__(16) __half g_xh [(size_t)MM * DM];
__device__ __align__(16) __half g_xvh[(size_t)MM * DI];       // conv+silu output (u)
__device__ __align__(16) __half g_dth[(size_t)MM * DTR];
__device__ __align__(16) __half g_ygh[(size_t)MM * DI];

// transposed fp16 weights, layout (N, K) row-major
__device__ __align__(16) __half g_winT[(size_t)(2*DI) * DM];
__device__ __align__(16) __half g_wxT[(size_t)128 * DI];      // rows 96..127 stay zero
__device__ __align__(16) __half g_wdtT[(size_t)DI * DTR];
__device__ __align__(16) __half g_woutT[(size_t)DM * DI];

// ===================== low-level helpers =====================
typedef unsigned long long ull;

__device__ __forceinline__ uint32_t smem_u32(const void* p) {
    uint32_t a;
    asm("{ .reg .u64 t; cvta.to.shared.u64 t, %1; cvt.u32.u64 %0, t; }" : "=r"(a) : "l"(p));
    return a;
}
__device__ __forceinline__ void cpa16(uint32_t s, const void* g) {
    asm volatile("cp.async.cg.shared.global [%0], [%1], 16;" :: "r"(s), "l"(g));
}
#define CP_COMMIT() asm volatile("cp.async.commit_group;")
#define CP_WAIT(n)  asm volatile("cp.async.wait_group %0;" :: "n"(n))

__device__ __forceinline__ void ldsm4(uint32_t* r, uint32_t addr) {
    asm volatile("ldmatrix.sync.aligned.m8n8.x4.shared.b16 {%0,%1,%2,%3}, [%4];"
        : "=r"(r[0]), "=r"(r[1]), "=r"(r[2]), "=r"(r[3]) : "r"(addr));
}
__device__ __forceinline__ void mma16816(float* d, const uint32_t* a, const uint32_t* b) {
    asm volatile(
        "mma.sync.aligned.m16n8k16.row.col.f32.f16.f16.f32 "
        "{%0,%1,%2,%3}, {%4,%5,%6,%7}, {%8,%9}, {%0,%1,%2,%3};"
        : "+f"(d[0]), "+f"(d[1]), "+f"(d[2]), "+f"(d[3])
        : "r"(a[0]), "r"(a[1]), "r"(a[2]), "r"(a[3]), "r"(b[0]), "r"(b[1]));
}
__device__ __forceinline__ float silu_f(float v) {
    return v * (1.0f / (1.0f + __expf(-v)));
}
__device__ __forceinline__ float softplus_f(float v) {
    return (v > 20.0f) ? v : __logf(1.0f + __expf(v));
}

// ---- packed f32x2 helpers ----
__device__ __forceinline__ ull pk2(float x, float y) {
    ull r; asm("mov.b64 %0, {%1, %2};" : "=l"(r) : "f"(x), "f"(y)); return r;
}
__device__ __forceinline__ void upk2(ull v, float& x, float& y) {
    asm("mov.b64 {%0, %1}, %2;" : "=f"(x), "=f"(y) : "l"(v));
}
__device__ __forceinline__ ull fma2(ull a, ull b, ull c) {
    ull d; asm("fma.rn.f32x2 %0, %1, %2, %3;" : "=l"(d) : "l"(a), "l"(b), "l"(c)); return d;
}
__device__ __forceinline__ ull mul2(ull a, ull b) {
    ull d; asm("mul.rn.f32x2 %0, %1, %2;" : "=l"(d) : "l"(a), "l"(b)); return d;
}

// ================= HMMA GEMM: C(M,N) = A(M,K) @ B(N,K)^T, fp16, 2-stage =================
#define ASZ 16384
#define STAGE 32768
#define HG_SMEM 65536

__global__ void __launch_bounds__(256, 2)
hgemm(const __half* __restrict__ A, const __half* __restrict__ B,
      float* __restrict__ C, __half* __restrict__ C2,
      int N, int K, int ldc,
      const float* __restrict__ bias, int epi, int kslice, size_t zstride)
{
    extern __shared__ char smem[];
    const uint32_t sb = smem_u32(smem);
    const int tid  = threadIdx.x;
    const int wid  = tid >> 5;
    const int lane = tid & 31;
    const int row0 = blockIdx.y * 128;
    const int col0 = blockIdx.x * 128;
    const int wm = wid & 1;
    const int wn = wid >> 1;

    const int kbase = blockIdx.z * kslice;
    C += (size_t)blockIdx.z * zstride;
    const int KT = kslice >> 6;

    float acc[4][4][4];
    #pragma unroll
    for (int i = 0; i < 4; i++)
        #pragma unroll
        for (int j = 0; j < 4; j++)
            #pragma unroll
            for (int q = 0; q < 4; q++) acc[i][j][q] = 0.0f;

    auto load_stage = [&](int s, int k0) {
        const uint32_t base = sb + (uint32_t)s * STAGE;
        #pragma unroll
        for (int i = 0; i < 4; i++) {
            const int lin = tid + i * 256;
            const int r = lin >> 3, c = lin & 7;
            const uint32_t so = (uint32_t)(r * 128 + ((c ^ (r & 7)) << 4));
            cpa16(base + so,       A + (size_t)(row0 + r) * K + k0 + c * 8);
            cpa16(base + ASZ + so, B + (size_t)(col0 + r) * K + k0 + c * 8);
        }
        CP_COMMIT();
    };

    auto compute_stage = [&](int s) {
        const uint32_t aBase = sb + (uint32_t)s * STAGE;
        const uint32_t bBase = aBase + ASZ;
        #pragma unroll
        for (int kss = 0; kss < 4; kss++) {
            const int ks = (kss + wid) & 3;
            uint32_t ah[4][4];
            #pragma unroll
            for (int mt = 0; mt < 4; mt++) {
                const int R = wm * 64 + mt * 16 + (lane & 15);
                const int c = ks * 2 + (lane >> 4);
                ldsm4(ah[mt], aBase + (uint32_t)(R * 128 + ((c ^ (R & 7)) << 4)));
            }
            #pragma unroll
            for (int g = 0; g < 2; g++) {
                const int R = wn * 32 + g * 16 + (lane & 7) + ((lane >> 4) & 1) * 8;
                const int c = ks * 2 + ((lane >> 3) & 1);
                uint32_t bh[4];
                ldsm4(bh, bBase + (uint32_t)(R * 128 + ((c ^ (R & 7)) << 4)));
                #pragma unroll
                for (int mt = 0; mt < 4; mt++)
                    #pragma unroll
                    for (int sub = 0; sub < 2; sub++)
                        mma16816(acc[mt][g * 2 + sub], ah[mt], &bh[sub * 2]);
            }
        }
    };

    load_stage(0, kbase);
    for (int kt = 0; kt < KT; kt++) {
        if (kt + 1 < KT) {
            load_stage((kt + 1) & 1, kbase + (kt + 1) * 64);
            CP_WAIT(1);
        } else {
            CP_WAIT(0);
        }
        __syncthreads();
        compute_stage(kt & 1);
        __syncthreads();
    }

    // epi: 0 = fp32 store; 1 = bias+softplus fp32 store;
    //      2 = split: x-half fp32 -> C (ldc), res-half silu -> fp16 C2
    const bool resblk = (epi == 2) && (col0 >= DI);
    #pragma unroll
    for (int mt = 0; mt < 4; mt++) {
        const int row = row0 + wm * 64 + mt * 16 + (lane >> 2);
        #pragma unroll
        for (int j = 0; j < 4; j++) {
            const int col = col0 + wn * 32 + j * 8 + (lane & 3) * 2;
            float v0 = acc[mt][j][0], v1 = acc[mt][j][1];
            float v2 = acc[mt][j][2], v3 = acc[mt][j][3];
            if (epi == 1) {
                const float b0 = bias[col], b1 = bias[col + 1];
                v0 = softplus_f(v0 + b0);
                v1 = softplus_f(v1 + b1);
                v2 = softplus_f(v2 + b0);
                v3 = softplus_f(v3 + b1);
            }
            if (resblk) {
                const int rc = col - DI;
                __half2 h0 = __floats2half2_rn(silu_f(v0), silu_f(v1));
                __half2 h1 = __floats2half2_rn(silu_f(v2), silu_f(v3));
                *(__half2*)(C2 + (size_t)row * DI + rc)       = h0;
                *(__half2*)(C2 + (size_t)(row + 8) * DI + rc) = h1;
            } else {
                *(float2*)(C + (size_t)row * ldc + col)       = make_float2(v0, v1);
                *(float2*)(C + (size_t)(row + 8) * ldc + col) = make_float2(v2, v3);
            }
        }
    }
}

// ---------------- split-K reduce for GEMM2 -> xdbl + fused dt fp16 ----------------
__global__ void __launch_bounds__(256)
reduceK(const float* __restrict__ part, float* __restrict__ xdbl, __half* __restrict__ dth)
{
    const int i = blockIdx.x * 256 + threadIdx.x;
    if (i >= MM * XDBL_W) return;
    const int r = i / XDBL_W, c = i - r * XDBL_W;
    const size_t o = (size_t)r * 128 + c;
    float s = 0.0f;
    #pragma unroll
    for (int q = 0; q < KSPL; q++) s += part[o + (size_t)q * MM * 128];
    xdbl[i] = s;
    if (c < DTR) dth[(size_t)r * DTR + c] = __float2half_rn(s);
}

// ---------------- mega-prep: all transposes + x->fp16 + A table in ONE launch ----------------
__device__ __forceinline__ void ttrans_tile(const float* __restrict__ W, __half* __restrict__ T,
                                            int K, int N, int bx, int by)
{
    __shared__ float t[32][33];
    const int n0 = bx * 32;
    const int k0 = by * 32;
    const int tx = threadIdx.x & 31;
    const int ty = threadIdx.x >> 5;
    #pragma unroll
    for (int i = 0; i < 32; i += 8)
        t[ty + i][tx] = W[(size_t)(k0 + ty + i) * N + (n0 + tx)];
    __syncthreads();
    #pragma unroll
    for (int i = 0; i < 32; i += 8)
        T[(size_t)(n0 + ty + i) * K + (k0 + tx)] = __float2half_rn(t[tx][ty + i]);
}

// job layout (block ranges):
//   [0, 4096)            ttrans W_in   (gx=128, gy=32)
//   [4096, 6144)         ttrans W_out  (gx=32,  gy=64)
//   [6144, 14336)        to_half x     (8192 blocks)
//   [14336, 14528)       ttrans W_x    (gx=3,   gy=64)
//   [14528, 14656)       ttrans W_dt   (gx=64,  gy=2)
//   [14656, 14784)       a_prep        (128 blocks)
#define PREP_BLOCKS 14784
__global__ void __launch_bounds__(256)
mega_prep(const float* __restrict__ x, const float* __restrict__ W_in,
          const float* __restrict__ W_x, const float* __restrict__ W_dt,
          const float* __restrict__ W_out, const float* __restrict__ logA,
          __half* __restrict__ xh, __half* __restrict__ winT, __half* __restrict__ wxT,
          __half* __restrict__ wdtT, __half* __restrict__ woutT, float* __restrict__ Atab)
{
    const int bid = blockIdx.x;
    if (bid < 4096) {
        ttrans_tile(W_in, winT, DM, 2*DI, bid & 127, bid >> 7);
    } else if (bid < 6144) {
        const int r = bid - 4096;
        ttrans_tile(W_out, woutT, DI, DM, r & 31, r >> 5);
    } else if (bid < 14336) {
        const int i = (bid - 6144) * 256 + threadIdx.x;     // MM*DM/4 = 2097152
        const float4 v = ((const float4*)x)[i];
        __half2 a = __floats2half2_rn(v.x, v.y);
        __half2 b = __floats2half2_rn(v.z, v.w);
        ((uint2*)xh)[i] = make_uint2(*(uint32_t*)&a, *(uint32_t*)&b);
    } else if (bid < 14528) {
        const int r = bid - 14336;
        ttrans_tile(W_x, wxT, DI, XDBL_W, r % 3, r / 3);
    } else if (bid < 14656) {
        const int r = bid - 14528;
        ttrans_tile(W_dt, wdtT, DTR, DI, r & 63, r >> 6);
    } else {
        const int i = (bid - 14656) * 256 + threadIdx.x;    // DS*DI = 32768
        const int d = i & (DI - 1);
        const int n = i >> 11;
        Atab[(size_t)n * DI + d] = -__expf(logA[(size_t)d * DS + n]);
    }
}

// ---------------- causal depthwise conv (k=4) + SiLU -> fp16, 8 outputs/thread ----------------
__global__ void __launch_bounds__(256)
conv_silu_kernel(const float* __restrict__ xc, const float* __restrict__ w,
                 const float* __restrict__ bias, __half* __restrict__ oh)
{
    const int d  = blockIdx.x * 256 + threadIdx.x;
    const int l0 = blockIdx.y * 8;
    const int b  = blockIdx.z;

    const float w0 = w[d * DC + 0], w1 = w[d * DC + 1], w2 = w[d * DC + 2], w3 = w[d * DC + 3];
    const float bv = bias[d];

    const size_t base = ((size_t)b * LL + l0) * DI + d;
    float xv[11];
    #pragma unroll
    for (int i = 0; i < 11; i++) {
        const int l = l0 + i - 3;
        xv[i] = (l >= 0) ? xc[base + (size_t)(i - 3) * DI] : 0.0f;
    }
    #pragma unroll
    for (int j = 0; j < 8; j++) {
        float acc = bv;
        acc = fmaf(xv[j + 0], w0, acc);
        acc = fmaf(xv[j + 1], w1, acc);
        acc = fmaf(xv[j + 2], w2, acc);
        acc = fmaf(xv[j + 3], w3, acc);
        oh[base + (size_t)j * DI] = __float2half_rn(silu_f(acc));
    }
}

// ================= chunked selective scan (NCH=32) =================
__device__ __forceinline__ void make_e2(bool pw, float dts, float A0, const float* A, ull* e2)
{
    if (pw) {
        const float e1 = __expf(dts * A0);
        const float es = e1 * e1;
        const ull es2 = pk2(es, es);
        e2[0] = pk2(e1, es);
        #pragma unroll
        for (int k = 1; k < 8; k++) e2[k] = mul2(e2[k - 1], es2);
    } else {
        #pragma unroll
        for (int k = 0; k < 8; k++)
            e2[k] = pk2(__expf(dts * A[2 * k]), __expf(dts * A[2 * k + 1]));
    }
}

__global__ void __launch_bounds__(256)
scan_p1(const float* __restrict__ dt, const __half* __restrict__ u,
        const float* __restrict__ xdbl, const float* __restrict__ Atab,
        float* __restrict__ H, float* __restrict__ P)
{
    __shared__ float sB[2][TS * 16];
    const int bid = blockIdx.x;
    const int tid = threadIdx.x;
    const int d = ((bid & 7) << 8) + tid;
    const int c = (bid >> 3) & (NCH - 1);
    const int b = bid >> (3 + NCHB);

    float A[DS];
    #pragma unroll
    for (int n = 0; n < DS; n++) A[n] = Atab[(size_t)n * DI + d];
    const float A0 = A[0];
    bool pw = true;
    #pragma unroll
    for (int n = 1; n < DS; n++)
        pw = pw && (fabsf(A[n] - (float)(n + 1) * A0) <= 1e-5f * fabsf(A[n]));

    ull h2[8];
    #pragma unroll
    for (int k = 0; k < 8; k++) h2[k] = 0ull;
    float sdt = 0.0f;

    const size_t m0 = (size_t)b * LL + c * CL;
    const uint32_t sbB0 = smem_u32(&sB[0][0]);
    const uint32_t sbB1 = smem_u32(&sB[1][0]);

    if (tid < 64) {
        const int step = tid >> 2, f = (tid & 3) * 4;
        cpa16(sbB0 + tid * 16, xdbl + (m0 + step) * XDBL_W + DTR + f);
    }
    CP_COMMIT();

    for (int t0 = 0; t0 < CL; t0 += TS) {
        const int buf = (t0 / TS) & 1;
        CP_WAIT(0);
        __syncthreads();
        if (t0 + TS < CL && tid < 64) {
            const int step = tid >> 2, f = (tid & 3) * 4;
            cpa16((buf ? sbB0 : sbB1) + tid * 16,
                  xdbl + (m0 + t0 + TS + step) * XDBL_W + DTR + f);
        }
        CP_COMMIT();

        float dtv[TS];
        __half uvh[TS];
        #pragma unroll
        for (int s = 0; s < TS; s++) dtv[s] = dt[(m0 + t0 + s) * DI + d];
        #pragma unroll
        for (int s = 0; s < TS; s++) uvh[s] = u[(m0 + t0 + s) * DI + d];

        #pragma unroll
        for (int s = 0; s < TS; s++) {
            const float dts = dtv[s];
            const float dtu = dts * __half2float(uvh[s]);
            sdt += dts;
            ull e2[8];
            make_e2(pw, dts, A0, A, e2);
            const ull dtu2 = pk2(dtu, dtu);
            const ull* B2 = (const ull*)&sB[buf][s * 16];
            #pragma unroll
            for (int k = 0; k < 8; k++)
                h2[k] = fma2(e2[k], h2[k], mul2(dtu2, B2[k]));
        }
    }
    const size_t o = ((size_t)(b * NCH + c) * DS) * DI + d;
    #pragma unroll
    for (int k = 0; k < 8; k++) {
        float hx, hy;
        upk2(h2[k], hx, hy);
        H[o + (size_t)(2 * k) * DI]     = hx;
        H[o + (size_t)(2 * k + 1) * DI] = hy;
    }
    #pragma unroll
    for (int n = 0; n < DS; n++)
        P[o + (size_t)n * DI] = __expf(A[n] * sdt);
}

__global__ void __launch_bounds__(256)
scan_mid(const float* __restrict__ H, const float* __restrict__ P, float* __restrict__ Hpre)
{
    const int idx = blockIdx.x * 256 + threadIdx.x;   // BB*DS*DI = 131072
    const int d = idx & (DI - 1);
    const int rest = idx >> 11;
    const int n = rest & (DS - 1);
    const int b = rest >> 4;

    float h = 0.0f;
    for (int c = 0; c < NCH; c++) {
        const size_t o = ((size_t)((b * NCH + c) * DS) + n) * DI + d;
        Hpre[o] = h;
        h = fmaf(P[o], h, H[o]);
    }
}

__global__ void __launch_bounds__(256)
scan_p2(const float* __restrict__ dt, const __half* __restrict__ u,
        const float* __restrict__ xdbl, const float* __restrict__ Atab,
        const float* __restrict__ Dp, const __half* __restrict__ resg,
        const float* __restrict__ Hpre,
        __half* __restrict__ ygh)
{
    __shared__ float sBC[2][TS * 32];
    const int bid = blockIdx.x;
    const int tid = threadIdx.x;
    const int d = ((bid & 7) << 8) + tid;
    const int c = (bid >> 3) & (NCH - 1);
    const int b = bid >> (3 + NCHB);

    float A[DS];
    #pragma unroll
    for (int n = 0; n < DS; n++) A[n] = Atab[(size_t)n * DI + d];
    const float A0 = A[0];
    bool pw = true;
    #pragma unroll
    for (int n = 1; n < DS; n++)
        pw = pw && (fabsf(A[n] - (float)(n + 1) * A0) <= 1e-5f * fabsf(A[n]));

    ull h2[8];
    {
        const size_t o = ((size_t)(b * NCH + c) * DS) * DI + d;
        #pragma unroll
        for (int k = 0; k < 8; k++)
            h2[k] = pk2(Hpre[o + (size_t)(2 * k) * DI], Hpre[o + (size_t)(2 * k + 1) * DI]);
    }
    const float Dv = Dp[d];
    const size_t m0 = (size_t)b * LL + c * CL;
    const uint32_t sb0 = smem_u32(&sBC[0][0]);
    const uint32_t sb1 = smem_u32(&sBC[1][0]);

    if (tid < 128) {
        const int step = tid >> 3, f = (tid & 7) * 4;
        cpa16(sb0 + tid * 16, xdbl + (m0 + step) * XDBL_W + DTR + f);
    }
    CP_COMMIT();

    for (int t0 = 0; t0 < CL; t0 += TS) {
        const int buf = (t0 / TS) & 1;
        CP_WAIT(0);
        __syncthreads();
        if (t0 + TS < CL && tid < 128) {
            const int step = tid >> 3, f = (tid & 7) * 4;
            cpa16((buf ? sb0 : sb1) + tid * 16,
                  xdbl + (m0 + t0 + TS + step) * XDBL_W + DTR + f);
        }
        CP_COMMIT();

        float dtv[TS];
        __half uvh[TS], gvh[TS];
        #pragma unroll
        for (int s = 0; s < TS; s++) dtv[s] = dt[(m0 + t0 + s) * DI + d];
        #pragma unroll
        for (int s = 0; s < TS; s++) uvh[s] = u[(m0 + t0 + s) * DI + d];
        #pragma unroll
        for (int s = 0; s < TS; s++) gvh[s] = resg[(m0 + t0 + s) * DI + d];

        #pragma unroll
        for (int s = 0; s < TS; s++) {
            const float dts = dtv[s];
            const float uv  = __half2float(uvh[s]);
            const float dtu = dts * uv;
            ull e2[8];
            make_e2(pw, dts, A0, A, e2);
            const ull dtu2 = pk2(dtu, dtu);
            const ull* B2 = (const ull*)&sBC[buf][s * 32];
            const ull* C2 = B2 + 8;
            ull y2 = 0ull;
            #pragma unroll
            for (int k = 0; k < 8; k++) {
                h2[k] = fma2(e2[k], h2[k], mul2(dtu2, B2[k]));
                y2 = fma2(C2[k], h2[k], y2);
            }
            float yx, yy;
            upk2(y2, yx, yy);
            float y = yx + yy;
            y = fmaf(Dv, uv, y);
            ygh[(m0 + t0 + s) * DI + d] = __float2half_rn(y * __half2float(gvh[s]));
        }
    }
}

// ---------------- host launcher ----------------
extern "C" void kernel_launch(void* const* d_in, const int* in_sizes, int n_in,
                              void* d_out, int out_size)
{
    const float* x      = (const float*)d_in[0];
    const float* W_in   = (const float*)d_in[1];
    const float* conv_w = (const float*)d_in[2];
    const float* conv_b = (const float*)d_in[3];
    const float* W_x    = (const float*)d_in[4];
    const float* W_dt   = (const float*)d_in[5];
    const float* b_dt   = (const float*)d_in[6];
    const float* logA   = (const float*)d_in[7];
    const float* Dp     = (const float*)d_in[8];
    const float* W_out  = (const float*)d_in[9];
    float* out = (float*)d_out;

    cudaFuncSetAttribute(hgemm, cudaFuncAttributeMaxDynamicSharedMemorySize, HG_SMEM);

    float *xc, *xdbl, *dtb, *Hb, *Pb, *Hpre, *Atab, *part;
    cudaGetSymbolAddress((void**)&xc,   g_xc);
    cudaGetSymbolAddress((void**)&xdbl, g_xdbl);
    cudaGetSymbolAddress((void**)&dtb,  g_dt);
    cudaGetSymbolAddress((void**)&Hb,   g_H);
    cudaGetSymbolAddress((void**)&Pb,   g_P);
    cudaGetSymbolAddress((void**)&Hpre, g_Hpre);
    cudaGetSymbolAddress((void**)&Atab, g_Atab);
    cudaGetSymbolAddress((void**)&part, g_part);

    __half *resg, *xh, *xvh, *dth, *ygh;
    cudaGetSymbolAddress((void**)&resg, g_resg);
    cudaGetSymbolAddress((void**)&xh,  g_xh);
    cudaGetSymbolAddress((void**)&xvh, g_xvh);
    cudaGetSymbolAddress((void**)&dth, g_dth);
    cudaGetSymbolAddress((void**)&ygh, g_ygh);

    __half *winT, *wxT, *wdtT, *woutT;
    cudaGetSymbolAddress((void**)&winT,  g_winT);
    cudaGetSymbolAddress((void**)&wxT,   g_wxT);
    cudaGetSymbolAddress((void**)&wdtT,  g_wdtT);
    cudaGetSymbolAddress((void**)&woutT, g_woutT);

    // 1) ALL prep in one launch (transposes + x->fp16 + A table)
    mega_prep<<<PREP_BLOCKS, 256>>>(x, W_in, W_x, W_dt, W_out, logA,
                                    xh, winT, wxT, wdtT, woutT, Atab);

    // 2) GEMM1: x @ W_in: x-half -> xc (fp32), res-half -> silu -> resg (fp16)
    hgemm<<<dim3((2*DI)/128, MM/128), 256, HG_SMEM>>>(
        xh, winT, xc, resg, 2*DI, DM, DI, nullptr, 2, DM, 0);

    // 3) causal conv + silu -> xvh (fp16), 8 outputs per thread
    conv_silu_kernel<<<dim3(DI/256, LL/8, BB), 256>>>(xc, conv_w, conv_b, xvh);

    // 4) GEMM2: xval @ W_x -> partials (split-K=8)
    hgemm<<<dim3(1, MM/128, KSPL), 256, HG_SMEM>>>(
        xvh, wxT, part, nullptr, 128, DI, 128, nullptr, 0, DI/KSPL, (size_t)MM*128);
    // 5) reduce -> xdbl + dt fp16
    reduceK<<<(MM*XDBL_W + 255)/256, 256>>>(part, xdbl, dth);

    // 6) GEMM3: softplus(dt_in @ W_dt + b_dt) -> dt
    hgemm<<<dim3(DI/128, MM/128), 256, HG_SMEM>>>(
        dth, wdtT, dtb, nullptr, DI, DTR, DI, b_dt, 1, DTR, 0);

    // 7-9) chunked selective scan
    scan_p1<<<BB * NCH * (DI/256), 256>>>(dtb, xvh, xdbl, Atab, Hb, Pb);
    scan_mid<<<(BB*DS*DI)/256, 256>>>(Hb, Pb, Hpre);
    scan_p2<<<BB * NCH * (DI/256), 256>>>(dtb, xvh, xdbl, Atab, Dp, resg, Hpre, ygh);

    // 10) GEMM4: yg @ W_out -> out
    hgemm<<<dim3(DM/128, MM/128), 256, HG_SMEM>>>(
        ygh, woutT, out, nullptr, DM, DI, DM, nullptr, 0, DI, 0);
}